// round 15
// baseline (speedup 1.0000x reference)
#include <cuda_runtime.h>
#include <cuda_fp16.h>
#include <cstdint>
#include <math.h>

#define S_  4
#define E_  8
#define D_  384
#define H1_ 160
#define H2_ 128
#define H3_ 96
#define N_  40000
#define TM  128
#define NTT 313
#define NB  ((N_ + 255) / 256)
#define NPART (NTT * S_ * 4)
#define MAXT 320
#define THREADS 512

typedef unsigned long long ull;
typedef uint32_t u32;
typedef unsigned short u16;

// ---------------- gmem image geometry ----------------
#define ACH   36864
#define ASE   (6 * ACH)
#define W1OFF 0
#define W2OFF 276480
#define W3OFF 370688
#define WSE   425984

__device__ int   g_is64;
__device__ int   g_blockCnt[NB * S_];
__device__ int   g_blockOff[NB * S_];
__device__ int   g_count[S_];
__device__ int   g_tbase[S_];
__device__ int   g_idx[S_ * N_];
__device__ float g_partial[NPART];
__device__ __align__(1024) unsigned char g_Wimg[(size_t)32 * WSE];
__device__ __align__(1024) unsigned char g_Aimg[(size_t)MAXT * ASE];

// ---------------- helpers ----------------
static __device__ __forceinline__ float celu_f(float x) {
    return x > 0.f ? x : 0.1f * (__expf(x * 10.f) - 1.f);
}
static __device__ __forceinline__ u32 s2u(const void* p) {
    u32 a;
    asm("{ .reg .u64 t; cvta.to.shared.u64 t, %1; cvt.u32.u64 %0, t; }" : "=r"(a) : "l"(p));
    return a;
}
static __device__ __forceinline__ void split2h(float v, u16& h, u16& l) {
    __half hb = __float2half_rn(v);
    float hf = __half2float(hb);
    __half lb = __float2half_rn(v - hf);
    h = __half_as_ushort(hb);
    l = __half_as_ushort(lb);
}
static __device__ __forceinline__ u32 packh(float x, float y) {
    u32 hh;
    asm("cvt.rn.f16x2.f32 %0, %1, %2;" : "=r"(hh) : "f"(y), "f"(x));
    return hh;
}
static __device__ __forceinline__ void mma_fp(float* c,
        u32 a0, u32 a1, u32 a2, u32 a3, u32 b0, u32 b1) {
    asm volatile(
        "mma.sync.aligned.m16n8k16.row.col.f32.f16.f16.f32 "
        "{%0,%1,%2,%3},{%4,%5,%6,%7},{%8,%9},{%0,%1,%2,%3};"
        : "+f"(c[0]), "+f"(c[1]), "+f"(c[2]), "+f"(c[3])
        : "r"(a0), "r"(a1), "r"(a2), "r"(a3), "r"(b0), "r"(b1));
}
#define CPA16(d, s) asm volatile("cp.async.cg.shared.global [%0], [%1], 16;" :: "r"(d), "l"(s) : "memory")
#define CPCOMMIT()  asm volatile("cp.async.commit_group;" ::: "memory")
#define CPWAIT(n)   asm volatile("cp.async.wait_group %0;" :: "n"(n) : "memory")

// ---------------- bucketing ----------------
__global__ void k_init(const ull* spq) {
    int tid = threadIdx.x;
    for (int i = tid; i < NPART; i += 256) g_partial[i] = 0.f;
    if (tid < 32) {
        ull v = spq[tid];
        int hiNZ = ((v >> 32) != 0ull) ? 1 : 0;
        int any = __any_sync(0xffffffffu, hiNZ);
        if (tid == 0) g_is64 = any ? 0 : 1;
    }
}
__global__ void k_count(const int* sp) {
    int tid = threadIdx.x, b = blockIdx.x;
    int n = b * 256 + tid;
    int shift = g_is64;
    int spv = -1;
    if (n < N_) spv = sp[(size_t)n << shift];
    __shared__ int wc[8][4];
    if (tid < 32) wc[tid >> 2][tid & 3] = 0;
    __syncthreads();
    unsigned mm = __match_any_sync(0xffffffffu, spv);
    int lane = tid & 31, w = tid >> 5;
    if (spv >= 0 && lane == (__ffs(mm) - 1)) wc[w][spv] = __popc(mm);
    __syncthreads();
    if (tid < 4) {
        int s = 0;
        for (int ww = 0; ww < 8; ww++) s += wc[ww][tid];
        g_blockCnt[b * 4 + tid] = s;
    }
}
__global__ void k_scan() {
    __shared__ int c[NB * 4];
    __shared__ int o[NB * 4];
    int tid = threadIdx.x;
    for (int i = tid; i < NB * 4; i += 256) c[i] = g_blockCnt[i];
    __syncthreads();
    if (tid == 0) {
        int r0 = 0, r1 = 0, r2 = 0, r3 = 0;
        for (int b = 0; b < NB; b++) {
            o[b * 4 + 0] = r0; r0 += c[b * 4 + 0];
            o[b * 4 + 1] = r1; r1 += c[b * 4 + 1];
            o[b * 4 + 2] = r2; r2 += c[b * 4 + 2];
            o[b * 4 + 3] = r3; r3 += c[b * 4 + 3];
        }
        g_count[0] = r0; g_count[1] = r1; g_count[2] = r2; g_count[3] = r3;
        int tb = 0;
        g_tbase[0] = 0;  tb += (r0 + TM - 1) / TM;
        g_tbase[1] = tb; tb += (r1 + TM - 1) / TM;
        g_tbase[2] = tb; tb += (r2 + TM - 1) / TM;
        g_tbase[3] = tb;
    }
    __syncthreads();
    for (int i = tid; i < NB * 4; i += 256) g_blockOff[i] = o[i];
}
__global__ void k_scatter(const int* sp) {
    int tid = threadIdx.x, b = blockIdx.x;
    int n = b * 256 + tid;
    int shift = g_is64;
    int spv = -1;
    if (n < N_) spv = sp[(size_t)n << shift];
    __shared__ int wc[8][4];
    __shared__ int woff[8][4];
    if (tid < 32) wc[tid >> 2][tid & 3] = 0;
    __syncthreads();
    unsigned mm = __match_any_sync(0xffffffffu, spv);
    int lane = tid & 31, w = tid >> 5;
    int rank = __popc(mm & ((1u << lane) - 1u));
    if (spv >= 0 && lane == (__ffs(mm) - 1)) wc[w][spv] = __popc(mm);
    __syncthreads();
    if (tid < 4) {
        int run = g_blockOff[b * 4 + tid];
        for (int ww = 0; ww < 8; ww++) { woff[ww][tid] = run; run += wc[ww][tid]; }
    }
    __syncthreads();
    if (spv >= 0) g_idx[spv * N_ + woff[w][spv] + rank] = n;
}

// ---------------- weight image prep ----------------
__global__ void k_wprep(const float* __restrict__ W1, const float* __restrict__ W2,
                        const float* __restrict__ W3) {
    int se = blockIdx.x;
    int tid0 = threadIdx.x + blockIdx.y * 256;
    const int step = 256 * 8;
    unsigned char* base = g_Wimg + (size_t)se * WSE;
    for (int i = tid0; i < D_ * H1_; i += step) {           // W1: single fp16
        int n = i % H1_, k = i / H1_;
        u16 h = __half_as_ushort(__float2half_rn(W1[((size_t)se * D_ + k) * H1_ + n]));
        int c = k >> 6, kl = k & 63;
        ((u16*)(base + W1OFF + c * 23040))[n * 72 + kl] = h;
    }
    for (int i = tid0; i < H1_ * H2_; i += step) {          // W2: single fp16
        int n = i % H2_, k = i / H2_;
        u16 h = __half_as_ushort(__float2half_rn(W2[((size_t)se * H1_ + k) * H2_ + n]));
        int c = k >> 6, kl = k & 63;
        int str = (c == 2) ? 40 : 72;
        int coff = (c == 0) ? 0 : (c == 1 ? 18432 : 36864);
        ((u16*)(base + W2OFF + coff))[n * str + kl] = h;
    }
    for (int i = tid0; i < H2_ * H3_; i += step) {          // W3: fp16 hi/lo
        int n = i % H3_, k = i / H3_;
        u16 h, l; split2h(W3[((size_t)se * H2_ + k) * H3_ + n], h, l);
        int c = k >> 6, kl = k & 63;
        u16* p = (u16*)(base + W3OFF + c * 27648);
        p[n * 72 + kl] = h;
        p[6912 + n * 72 + kl] = l;
    }
}

// ---------------- A image prep: gather + single fp16 (hi only) ----------------
__global__ void k_aprep(const float* __restrict__ aev) {
    int t = blockIdx.x, s = blockIdx.y, tid = threadIdx.x;
    int cnt = g_count[s];
    int ntl = (cnt + TM - 1) / TM;
    if (t >= ntl) return;
    int gt = g_tbase[s] + t;
    __shared__ int sidx[TM];
    if (tid < TM) {
        int p = t * TM + tid; if (p >= cnt) p = cnt - 1;
        sidx[tid] = g_idx[s * N_ + p];
    }
    __syncthreads();
    unsigned char* base = g_Aimg + (size_t)gt * ASE;
    for (int i = tid; i < TM * (D_ / 2); i += 256) {
        int m = i / (D_ / 2), k = (i % (D_ / 2)) * 2;
        float2 v = *(const float2*)(aev + (size_t)sidx[m] * D_ + k);
        u32 h = packh(v.x, v.y);
        int c = k >> 6, kl = k & 63;
        u16* ch = (u16*)(base + c * ACH);
        *(u32*)(ch + m * 72 + kl) = h;
    }
}

// ---------------- fp16 single-term fragment GEMM (L1, L2) ----------------
template<int NT>
static __device__ __forceinline__ void chunk_mma1(
    float (*acc)[NT][4],
    const u16* Ah, int astr,
    const u16* Wh, int wstr,
    int ksteps, int mbase, int nbase, int g, int q)
{
    for (int ks = 0; ks < ksteps; ks++) {
        const int k0 = ks * 16;
        u32 ah[2][4];
#pragma unroll
        for (int mt = 0; mt < 2; mt++) {
            const u16* ap = Ah + (mbase + mt * 16 + g) * astr + k0 + q * 2;
            ah[mt][0] = *(const u32*)(ap);
            ah[mt][1] = *(const u32*)(ap + 8 * astr);
            ah[mt][2] = *(const u32*)(ap + 8);
            ah[mt][3] = *(const u32*)(ap + 8 * astr + 8);
        }
#pragma unroll
        for (int nt = 0; nt < NT; nt++) {
            const u16* wp = Wh + (nbase + nt * 8 + g) * wstr + k0 + q * 2;
            u32 b0 = *(const u32*)(wp);
            u32 b1 = *(const u32*)(wp + 8);
            mma_fp(acc[0][nt], ah[0][0], ah[0][1], ah[0][2], ah[0][3], b0, b1);
            mma_fp(acc[1][nt], ah[1][0], ah[1][1], ah[1][2], ah[1][3], b0, b1);
        }
    }
}

// ---------------- fp16 2-term-W fragment GEMM (L3): ah*wh + ah*wl ----------------
template<int NT>
static __device__ __forceinline__ void chunk_mma_w2(
    float (*acc)[NT][4],
    const u16* Ah, int astr,
    const u16* Wh, const u16* Wl, int wstr,
    int ksteps, int mbase, int nbase, int g, int q)
{
    for (int ks = 0; ks < ksteps; ks++) {
        const int k0 = ks * 16;
        u32 ah[2][4];
#pragma unroll
        for (int mt = 0; mt < 2; mt++) {
            const u16* ap = Ah + (mbase + mt * 16 + g) * astr + k0 + q * 2;
            ah[mt][0] = *(const u32*)(ap);
            ah[mt][1] = *(const u32*)(ap + 8 * astr);
            ah[mt][2] = *(const u32*)(ap + 8);
            ah[mt][3] = *(const u32*)(ap + 8 * astr + 8);
        }
#pragma unroll
        for (int nt = 0; nt < NT; nt++) {           // term 1: ah * wh
            const u16* wp = Wh + (nbase + nt * 8 + g) * wstr + k0 + q * 2;
            u32 b0 = *(const u32*)(wp);
            u32 b1 = *(const u32*)(wp + 8);
            mma_fp(acc[0][nt], ah[0][0], ah[0][1], ah[0][2], ah[0][3], b0, b1);
            mma_fp(acc[1][nt], ah[1][0], ah[1][1], ah[1][2], ah[1][3], b0, b1);
        }
#pragma unroll
        for (int nt = 0; nt < NT; nt++) {           // term 2: ah * wl (a cached)
            const u16* wq = Wl + (nbase + nt * 8 + g) * wstr + k0 + q * 2;
            u32 b0 = *(const u32*)(wq);
            u32 b1 = *(const u32*)(wq + 8);
            mma_fp(acc[0][nt], ah[0][0], ah[0][1], ah[0][2], ah[0][3], b0, b1);
            mma_fp(acc[1][nt], ah[1][0], ah[1][1], ah[1][2], ah[1][3], b0, b1);
        }
    }
}

// ---------------- main kernel ----------------
// De-aliased SMEM layout (enables aggressive copy prescheduling):
//  STG0 @0, STG1 @41472  (Ah 18432 | W1 23040 each) .. 82944
//  H1 (fp16 hi): c0 @82944 [128][72], c1 @101376, c2 @119808 [128][40] .. 130048
//  WB @130048 (55296: W2 batch 47104 or W3 batch 55296) .. 185344
//  H2 (fp16 hi): c0 @185344, c1 @203776 .. 222208
//  MISC @222208 .. SMEMB 226304 (< 227 KB opt-in cap)
#define SSTG  41472
#define H1B   82944
#define WB    130048
#define H2B   185344
#define MISCO 222208
#define SMEMB (MISCO + 4096)

__global__ void __launch_bounds__(THREADS, 1) k_main(
    const float* __restrict__ b1, const float* __restrict__ b2,
    const float* __restrict__ b3, const float* __restrict__ W4,
    const float* __restrict__ b4)
{
    extern __shared__ __align__(16) unsigned char sm[];
    const int s = blockIdx.y, t = blockIdx.x, z = blockIdx.z, tid = threadIdx.x;
    const int cnt = g_count[s];
    const int ntl = (cnt + TM - 1) / TM;
    if (t >= ntl) return;
    const int nvalid = min(TM, cnt - t * TM);
    const int gt = g_tbase[s] + t;
    const int lane = tid & 31, w = tid >> 5;
    const int wm = w & 3, wn = w >> 2, g = lane >> 2, q = lane & 3;
    const int mbase = wm * 32;
    const u32 sb = s2u(sm);
    float* b1s = (float*)(sm + MISCO);
    float* b2s = b1s + 160;
    float* b3s = b2s + 128;
    float* w4s = b3s + 96;
    float* part = w4s + 96;

    const unsigned char* Ab = g_Aimg + (size_t)gt * ASE;
    float blockSum = 0.f;

    const int h1off[3] = {H1B, H1B + 18432, H1B + 36864};
    const int h1str[3] = {72, 72, 40};
    const int w2off[3] = {0, 18432, 36864};
    const int w2str[3] = {72, 72, 40};
    const int w2ks[3]  = {4, 4, 2};

    auto cpyW = [&](const unsigned char* src, int bytes, u32 dstoff) {
        for (int i = tid * 16; i < bytes; i += THREADS * 16) CPA16(sb + dstoff + i, src + i);
        CPCOMMIT();
    };
    auto cpyL1 = [&](const unsigned char* WbX, int c, int bf) {
        u32 dst = sb + (bf ? SSTG : 0);
        const unsigned char* gA = Ab + c * ACH;                // hi half only
        for (int i = tid * 16; i < 18432; i += THREADS * 16) CPA16(dst + i, gA + i);
        const unsigned char* gW = WbX + W1OFF + c * 23040;
        for (int i = tid * 16; i < 23040; i += THREADS * 16) CPA16(dst + 18432 + i, gW + i);
        CPCOMMIT();
    };

    const unsigned char* Wb0 = g_Wimg + (size_t)(s * E_ + z * 2) * WSE;
    const unsigned char* Wb1 = Wb0 + WSE;

    // prime member-0 chunks 0,1
    cpyL1(Wb0, 0, 0);
    cpyL1(Wb0, 1, 1);

    for (int ei = 0; ei < 2; ei++) {
        const int se = s * E_ + z * 2 + ei;
        const unsigned char* Wb = ei ? Wb1 : Wb0;
        if (tid < 160) b1s[tid] = b1[se * H1_ + tid];
        if (tid < 128) b2s[tid] = b2[se * H2_ + tid];
        if (tid < 96) { b3s[tid] = b3[se * H3_ + tid]; w4s[tid] = W4[se * H3_ + tid]; }

        // ========= Layer 1 (K=384, N=160): fp16 single-term, NT=5 per warp =========
        float acc1[2][5][4];
#pragma unroll
        for (int a = 0; a < 2; a++)
#pragma unroll
            for (int b = 0; b < 5; b++)
#pragma unroll
                for (int c = 0; c < 4; c++) acc1[a][b][c] = 0.f;

        for (int kc = 0; kc < 6; kc++) {
            CPWAIT(1);
            __syncthreads();
            // stage0 is dead after kc=4's trailing barrier -> prefetch next member's c0 here
            if (ei == 0 && kc == 5) cpyL1(Wb1, 0, 0);
            const unsigned char* st = sm + ((kc & 1) ? SSTG : 0);
            chunk_mma1<5>(acc1, (const u16*)st, 72,
                          (const u16*)(st + 18432), 72,
                          4, mbase, wn * 40, g, q);
            __syncthreads();
            if (kc < 4)       cpyL1(Wb, kc + 2, kc & 1);
            else if (kc == 4) cpyW(Wb + W2OFF, 47104, WB);   // hidden under kc=5 compute
        }
        if (ei == 0) cpyL1(Wb1, 1, 1);                       // stage1 dead after kc=5 barrier

        // epilogue -> H1 (fp16 hi only, own region)
#pragma unroll
        for (int mt = 0; mt < 2; mt++)
#pragma unroll
            for (int nt = 0; nt < 5; nt++) {
                int n0 = wn * 40 + nt * 8 + q * 2;
                int cb = n0 >> 6, off = n0 & 63;
                u16* Hh = (u16*)(sm + h1off[cb]);
                int str = h1str[cb];
                int row = mbase + mt * 16 + g;
                *(u32*)(Hh + row * str + off) =
                    packh(celu_f(acc1[mt][nt][0] + b1s[n0]),
                          celu_f(acc1[mt][nt][1] + b1s[n0 + 1]));
                *(u32*)(Hh + (row + 8) * str + off) =
                    packh(celu_f(acc1[mt][nt][2] + b1s[n0]),
                          celu_f(acc1[mt][nt][3] + b1s[n0 + 1]));
            }
        if (ei == 0) { CPWAIT(2); } else { CPWAIT(0); }      // ensure W2 (allow c0',c1')
        __syncthreads();

        // ========= Layer 2 (K=160, N=128): fp16 single-term, NT=4 =========
        float acc2[2][4][4];
#pragma unroll
        for (int a = 0; a < 2; a++)
#pragma unroll
            for (int b = 0; b < 4; b++)
#pragma unroll
                for (int c = 0; c < 4; c++) acc2[a][b][c] = 0.f;

        for (int kc = 0; kc < 3; kc++) {
            chunk_mma1<4>(acc2,
                          (const u16*)(sm + h1off[kc]), h1str[kc],
                          (const u16*)(sm + WB + w2off[kc]), w2str[kc],
                          w2ks[kc], mbase, wn * 32, g, q);
        }
        __syncthreads();                                      // all warps done reading WB
        cpyW(Wb + W3OFF, 55296, WB);                          // overlaps epilogue-2

        // epilogue -> H2 (fp16 hi only, own region)
#pragma unroll
        for (int mt = 0; mt < 2; mt++)
#pragma unroll
            for (int nt = 0; nt < 4; nt++) {
                int n0 = wn * 32 + nt * 8 + q * 2;
                int cb = n0 >> 6, off = n0 & 63;
                u16* Hh = (u16*)(sm + H2B + cb * 18432);
                int row = mbase + mt * 16 + g;
                *(u32*)(Hh + row * 72 + off) =
                    packh(celu_f(acc2[mt][nt][0] + b2s[n0]),
                          celu_f(acc2[mt][nt][1] + b2s[n0 + 1]));
                *(u32*)(Hh + (row + 8) * 72 + off) =
                    packh(celu_f(acc2[mt][nt][2] + b2s[n0]),
                          celu_f(acc2[mt][nt][3] + b2s[n0 + 1]));
            }
        CPWAIT(0);
        __syncthreads();

        // ========= Layer 3 (K=128, N=96): fp16 2-term-W, NT=3 =========
        float acc3[2][3][4];
#pragma unroll
        for (int a = 0; a < 2; a++)
#pragma unroll
            for (int b = 0; b < 3; b++)
#pragma unroll
                for (int c = 0; c < 4; c++) acc3[a][b][c] = 0.f;

        for (int kc = 0; kc < 2; kc++) {
            const unsigned char* wb = sm + WB + kc * 27648;
            chunk_mma_w2<3>(acc3,
                            (const u16*)(sm + H2B + kc * 18432), 72,
                            (const u16*)wb, (const u16*)wb + 6912, 72,
                            4, mbase, wn * 24, g, q);
        }
        // ========= fused L3-epilogue + Layer 4 =========
        {
            float p00 = 0.f, p01 = 0.f, p10 = 0.f, p11 = 0.f;
#pragma unroll
            for (int nt = 0; nt < 3; nt++) {
                int n0 = wn * 24 + nt * 8 + q * 2;
                float w0 = w4s[n0], w1 = w4s[n0 + 1];
                float bb0 = b3s[n0], bb1 = b3s[n0 + 1];
                p00 += celu_f(acc3[0][nt][0] + bb0) * w0 + celu_f(acc3[0][nt][1] + bb1) * w1;
                p01 += celu_f(acc3[0][nt][2] + bb0) * w0 + celu_f(acc3[0][nt][3] + bb1) * w1;
                p10 += celu_f(acc3[1][nt][0] + bb0) * w0 + celu_f(acc3[1][nt][1] + bb1) * w1;
                p11 += celu_f(acc3[1][nt][2] + bb0) * w0 + celu_f(acc3[1][nt][3] + bb1) * w1;
            }
            p00 += __shfl_xor_sync(0xffffffffu, p00, 1); p00 += __shfl_xor_sync(0xffffffffu, p00, 2);
            p01 += __shfl_xor_sync(0xffffffffu, p01, 1); p01 += __shfl_xor_sync(0xffffffffu, p01, 2);
            p10 += __shfl_xor_sync(0xffffffffu, p10, 1); p10 += __shfl_xor_sync(0xffffffffu, p10, 2);
            p11 += __shfl_xor_sync(0xffffffffu, p11, 1); p11 += __shfl_xor_sync(0xffffffffu, p11, 2);
            if (q == 0) {
                part[wn * 128 + mbase + g]          = p00;
                part[wn * 128 + mbase + g + 8]      = p01;
                part[wn * 128 + mbase + 16 + g]     = p10;
                part[wn * 128 + mbase + 16 + g + 8] = p11;
            }
        }
        __syncthreads();
        if (tid < 128) {
            float en = part[tid] + part[128 + tid] + part[256 + tid] + part[384 + tid] + b4[se];
            part[tid] = (tid < nvalid) ? en : 0.f;
        }
        __syncthreads();
        if (tid < 32) {
            float v = part[tid] + part[tid + 32] + part[tid + 64] + part[tid + 96];
            for (int o = 16; o; o >>= 1) v += __shfl_down_sync(0xffffffffu, v, o);
            if (tid == 0) blockSum += v;
        }
        __syncthreads();
    }
    if (tid == 0) g_partial[(s * NTT + t) * 4 + z] = blockSum;
}

// ---------------- final reduction ----------------
__global__ void k_reduce(float* out) {
    __shared__ double sb[256];
    int tid = threadIdx.x;
    double s = 0.0;
    for (int i = tid; i < NPART; i += 256) s += (double)g_partial[i];
    sb[tid] = s;
    __syncthreads();
    for (int st = 128; st; st >>= 1) {
        if (tid < st) sb[tid] += sb[tid + st];
        __syncthreads();
    }
    if (tid == 0) out[0] = (float)(sb[0] * (1.0 / E_));
}

// ---------------- launch ----------------
extern "C" void kernel_launch(void* const* d_in, const int* in_sizes, int n_in,
                              void* d_out, int out_size)
{
    const void*  sp  = d_in[0];
    const float* aev = (const float*)d_in[1];
    const float* W1  = (const float*)d_in[2];
    const float* b1  = (const float*)d_in[3];
    const float* W2  = (const float*)d_in[4];
    const float* b2  = (const float*)d_in[5];
    const float* W3  = (const float*)d_in[6];
    const float* b3  = (const float*)d_in[7];
    const float* W4  = (const float*)d_in[8];
    const float* b4  = (const float*)d_in[9];

    cudaFuncSetAttribute(k_main, cudaFuncAttributeMaxDynamicSharedMemorySize, SMEMB);

    k_init<<<1, 256>>>((const ull*)sp);
    k_count<<<NB, 256>>>((const int*)sp);
    k_scan<<<1, 256>>>();
    k_scatter<<<NB, 256>>>((const int*)sp);
    dim3 gw(32, 8);
    k_wprep<<<gw, 256>>>(W1, W2, W3);
    dim3 ga(NTT, S_);
    k_aprep<<<ga, 256>>>(aev);
    dim3 gm(NTT, S_, 4);
    k_main<<<gm, THREADS, SMEMB>>>(b1, b2, b3, W4, b4);
    k_reduce<<<1, 256>>>((float*)d_out);
}

// round 16
// speedup vs baseline: 1.0232x; 1.0232x over previous
#include <cuda_runtime.h>
#include <cuda_fp16.h>
#include <cstdint>
#include <math.h>

#define S_  4
#define E_  8
#define D_  384
#define H1_ 160
#define H2_ 128
#define H3_ 96
#define N_  40000
#define TM  128
#define NTT 313
#define NB  ((N_ + 255) / 256)
#define NPART (NTT * S_ * 4)
#define MAXT 320
#define THREADS 512

typedef unsigned long long ull;
typedef uint32_t u32;
typedef unsigned short u16;

// ---------------- gmem image geometry ----------------
// A tiles: 6 chunks x (Ah [128][72] f16 18432 B | (lo half unused))
#define ACH   36864
#define ASE   (6 * ACH)
// Weights per (s,e):
//  W1 @0:      6 chunks x 23040, single fp16 [160][72]
//  W2 @276480: single fp16; c0@+0 18432 [128][72], c1@+18432 18432, c2@+36864 10240 [128][40]  (47104 total)
//  W3 @370688: fp16 hi/lo; 2 chunks x 27648 (hi 13824 | lo 13824), [96][72]  (55296 total)
#define W1OFF 0
#define W2OFF 276480
#define W3OFF 370688
#define WSE   425984

__device__ int   g_is64;
__device__ int   g_blockCnt[NB * S_];
__device__ int   g_blockOff[NB * S_];
__device__ int   g_count[S_];
__device__ int   g_tbase[S_];
__device__ int   g_idx[S_ * N_];
__device__ float g_partial[NPART];
__device__ __align__(1024) unsigned char g_Wimg[(size_t)32 * WSE];
__device__ __align__(1024) unsigned char g_Aimg[(size_t)MAXT * ASE];

// ---------------- helpers ----------------
static __device__ __forceinline__ float celu_f(float x) {
    return x > 0.f ? x : 0.1f * (__expf(x * 10.f) - 1.f);
}
static __device__ __forceinline__ u32 s2u(const void* p) {
    u32 a;
    asm("{ .reg .u64 t; cvta.to.shared.u64 t, %1; cvt.u32.u64 %0, t; }" : "=r"(a) : "l"(p));
    return a;
}
// fp16 hi/lo split of a scalar
static __device__ __forceinline__ void split2h(float v, u16& h, u16& l) {
    __half hb = __float2half_rn(v);
    float hf = __half2float(hb);
    __half lb = __float2half_rn(v - hf);
    h = __half_as_ushort(hb);
    l = __half_as_ushort(lb);
}
// fp32 pair -> packed f16x2 (hi only)
static __device__ __forceinline__ u32 packh(float x, float y) {
    u32 hh;
    asm("cvt.rn.f16x2.f32 %0, %1, %2;" : "=r"(hh) : "f"(y), "f"(x));
    return hh;
}
static __device__ __forceinline__ void mma_fp(float* c,
        u32 a0, u32 a1, u32 a2, u32 a3, u32 b0, u32 b1) {
    asm volatile(
        "mma.sync.aligned.m16n8k16.row.col.f32.f16.f16.f32 "
        "{%0,%1,%2,%3},{%4,%5,%6,%7},{%8,%9},{%0,%1,%2,%3};"
        : "+f"(c[0]), "+f"(c[1]), "+f"(c[2]), "+f"(c[3])
        : "r"(a0), "r"(a1), "r"(a2), "r"(a3), "r"(b0), "r"(b1));
}
#define CPA16(d, s) asm volatile("cp.async.cg.shared.global [%0], [%1], 16;" :: "r"(d), "l"(s) : "memory")
#define CPCOMMIT()  asm volatile("cp.async.commit_group;" ::: "memory")
#define CPWAIT(n)   asm volatile("cp.async.wait_group %0;" :: "n"(n) : "memory")

// ---------------- bucketing ----------------
__global__ void k_init(const ull* spq) {
    int tid = threadIdx.x;
    for (int i = tid; i < NPART; i += 256) g_partial[i] = 0.f;
    if (tid < 32) {
        ull v = spq[tid];
        int hiNZ = ((v >> 32) != 0ull) ? 1 : 0;
        int any = __any_sync(0xffffffffu, hiNZ);
        if (tid == 0) g_is64 = any ? 0 : 1;
    }
}
__global__ void k_count(const int* sp) {
    int tid = threadIdx.x, b = blockIdx.x;
    int n = b * 256 + tid;
    int shift = g_is64;
    int spv = -1;
    if (n < N_) spv = sp[(size_t)n << shift];
    __shared__ int wc[8][4];
    if (tid < 32) wc[tid >> 2][tid & 3] = 0;
    __syncthreads();
    unsigned mm = __match_any_sync(0xffffffffu, spv);
    int lane = tid & 31, w = tid >> 5;
    if (spv >= 0 && lane == (__ffs(mm) - 1)) wc[w][spv] = __popc(mm);
    __syncthreads();
    if (tid < 4) {
        int s = 0;
        for (int ww = 0; ww < 8; ww++) s += wc[ww][tid];
        g_blockCnt[b * 4 + tid] = s;
    }
}
__global__ void k_scan() {
    __shared__ int c[NB * 4];
    __shared__ int o[NB * 4];
    int tid = threadIdx.x;
    for (int i = tid; i < NB * 4; i += 256) c[i] = g_blockCnt[i];
    __syncthreads();
    if (tid == 0) {
        int r0 = 0, r1 = 0, r2 = 0, r3 = 0;
        for (int b = 0; b < NB; b++) {
            o[b * 4 + 0] = r0; r0 += c[b * 4 + 0];
            o[b * 4 + 1] = r1; r1 += c[b * 4 + 1];
            o[b * 4 + 2] = r2; r2 += c[b * 4 + 2];
            o[b * 4 + 3] = r3; r3 += c[b * 4 + 3];
        }
        g_count[0] = r0; g_count[1] = r1; g_count[2] = r2; g_count[3] = r3;
        int tb = 0;
        g_tbase[0] = 0;  tb += (r0 + TM - 1) / TM;
        g_tbase[1] = tb; tb += (r1 + TM - 1) / TM;
        g_tbase[2] = tb; tb += (r2 + TM - 1) / TM;
        g_tbase[3] = tb;
    }
    __syncthreads();
    for (int i = tid; i < NB * 4; i += 256) g_blockOff[i] = o[i];
}
__global__ void k_scatter(const int* sp) {
    int tid = threadIdx.x, b = blockIdx.x;
    int n = b * 256 + tid;
    int shift = g_is64;
    int spv = -1;
    if (n < N_) spv = sp[(size_t)n << shift];
    __shared__ int wc[8][4];
    __shared__ int woff[8][4];
    if (tid < 32) wc[tid >> 2][tid & 3] = 0;
    __syncthreads();
    unsigned mm = __match_any_sync(0xffffffffu, spv);
    int lane = tid & 31, w = tid >> 5;
    int rank = __popc(mm & ((1u << lane) - 1u));
    if (spv >= 0 && lane == (__ffs(mm) - 1)) wc[w][spv] = __popc(mm);
    __syncthreads();
    if (tid < 4) {
        int run = g_blockOff[b * 4 + tid];
        for (int ww = 0; ww < 8; ww++) { woff[ww][tid] = run; run += wc[ww][tid]; }
    }
    __syncthreads();
    if (spv >= 0) g_idx[spv * N_ + woff[w][spv] + rank] = n;
}

// ---------------- weight image prep ----------------
__global__ void k_wprep(const float* __restrict__ W1, const float* __restrict__ W2,
                        const float* __restrict__ W3) {
    int se = blockIdx.x;
    int tid0 = threadIdx.x + blockIdx.y * 256;
    const int step = 256 * 8;
    unsigned char* base = g_Wimg + (size_t)se * WSE;
    for (int i = tid0; i < D_ * H1_; i += step) {           // W1: single fp16
        int n = i % H1_, k = i / H1_;
        u16 h = __half_as_ushort(__float2half_rn(W1[((size_t)se * D_ + k) * H1_ + n]));
        int c = k >> 6, kl = k & 63;
        ((u16*)(base + W1OFF + c * 23040))[n * 72 + kl] = h;
    }
    for (int i = tid0; i < H1_ * H2_; i += step) {          // W2: single fp16
        int n = i % H2_, k = i / H2_;
        u16 h = __half_as_ushort(__float2half_rn(W2[((size_t)se * H1_ + k) * H2_ + n]));
        int c = k >> 6, kl = k & 63;
        int str = (c == 2) ? 40 : 72;
        int coff = (c == 0) ? 0 : (c == 1 ? 18432 : 36864);
        ((u16*)(base + W2OFF + coff))[n * str + kl] = h;
    }
    for (int i = tid0; i < H2_ * H3_; i += step) {          // W3: fp16 hi/lo
        int n = i % H3_, k = i / H3_;
        u16 h, l; split2h(W3[((size_t)se * H2_ + k) * H3_ + n], h, l);
        int c = k >> 6, kl = k & 63;
        u16* p = (u16*)(base + W3OFF + c * 27648);
        p[n * 72 + kl] = h;
        p[6912 + n * 72 + kl] = l;
    }
}

// ---------------- A image prep: gather + single fp16 (hi only) ----------------
__global__ void k_aprep(const float* __restrict__ aev) {
    int t = blockIdx.x, s = blockIdx.y, tid = threadIdx.x;
    int cnt = g_count[s];
    int ntl = (cnt + TM - 1) / TM;
    if (t >= ntl) return;
    int gt = g_tbase[s] + t;
    __shared__ int sidx[TM];
    if (tid < TM) {
        int p = t * TM + tid; if (p >= cnt) p = cnt - 1;
        sidx[tid] = g_idx[s * N_ + p];
    }
    __syncthreads();
    unsigned char* base = g_Aimg + (size_t)gt * ASE;
    for (int i = tid; i < TM * (D_ / 2); i += 256) {
        int m = i / (D_ / 2), k = (i % (D_ / 2)) * 2;
        float2 v = *(const float2*)(aev + (size_t)sidx[m] * D_ + k);
        u32 h = packh(v.x, v.y);
        int c = k >> 6, kl = k & 63;
        u16* ch = (u16*)(base + c * ACH);
        *(u32*)(ch + m * 72 + kl) = h;
    }
}

// ---------------- fp16 single-term fragment GEMM (L1, L2) ----------------
template<int NT>
static __device__ __forceinline__ void chunk_mma1(
    float (*acc)[NT][4],
    const u16* Ah, int astr,
    const u16* Wh, int wstr,
    int ksteps, int mbase, int nbase, int g, int q)
{
    for (int ks = 0; ks < ksteps; ks++) {
        const int k0 = ks * 16;
        u32 ah[2][4];
#pragma unroll
        for (int mt = 0; mt < 2; mt++) {
            const u16* ap = Ah + (mbase + mt * 16 + g) * astr + k0 + q * 2;
            ah[mt][0] = *(const u32*)(ap);
            ah[mt][1] = *(const u32*)(ap + 8 * astr);
            ah[mt][2] = *(const u32*)(ap + 8);
            ah[mt][3] = *(const u32*)(ap + 8 * astr + 8);
        }
#pragma unroll
        for (int nt = 0; nt < NT; nt++) {
            const u16* wp = Wh + (nbase + nt * 8 + g) * wstr + k0 + q * 2;
            u32 b0 = *(const u32*)(wp);
            u32 b1 = *(const u32*)(wp + 8);
            mma_fp(acc[0][nt], ah[0][0], ah[0][1], ah[0][2], ah[0][3], b0, b1);
            mma_fp(acc[1][nt], ah[1][0], ah[1][1], ah[1][2], ah[1][3], b0, b1);
        }
    }
}

// ---------------- fp16 2-term-W fragment GEMM (L3): ah*wh + ah*wl ----------------
template<int NT>
static __device__ __forceinline__ void chunk_mma_w2(
    float (*acc)[NT][4],
    const u16* Ah, int astr,
    const u16* Wh, const u16* Wl, int wstr,
    int ksteps, int mbase, int nbase, int g, int q)
{
    for (int ks = 0; ks < ksteps; ks++) {
        const int k0 = ks * 16;
        u32 ah[2][4];
#pragma unroll
        for (int mt = 0; mt < 2; mt++) {
            const u16* ap = Ah + (mbase + mt * 16 + g) * astr + k0 + q * 2;
            ah[mt][0] = *(const u32*)(ap);
            ah[mt][1] = *(const u32*)(ap + 8 * astr);
            ah[mt][2] = *(const u32*)(ap + 8);
            ah[mt][3] = *(const u32*)(ap + 8 * astr + 8);
        }
#pragma unroll
        for (int nt = 0; nt < NT; nt++) {           // term 1: ah * wh
            const u16* wp = Wh + (nbase + nt * 8 + g) * wstr + k0 + q * 2;
            u32 b0 = *(const u32*)(wp);
            u32 b1 = *(const u32*)(wp + 8);
            mma_fp(acc[0][nt], ah[0][0], ah[0][1], ah[0][2], ah[0][3], b0, b1);
            mma_fp(acc[1][nt], ah[1][0], ah[1][1], ah[1][2], ah[1][3], b0, b1);
        }
#pragma unroll
        for (int nt = 0; nt < NT; nt++) {           // term 2: ah * wl (a cached)
            const u16* wq = Wl + (nbase + nt * 8 + g) * wstr + k0 + q * 2;
            u32 b0 = *(const u32*)(wq);
            u32 b1 = *(const u32*)(wq + 8);
            mma_fp(acc[0][nt], ah[0][0], ah[0][1], ah[0][2], ah[0][3], b0, b1);
            mma_fp(acc[1][nt], ah[1][0], ah[1][1], ah[1][2], ah[1][3], b0, b1);
        }
    }
}

// ---------------- main kernel ----------------
// SMEM: L1 stages @0, @41472 (Ah 18432 | W1 23040 each; end 82944, dead before H1).
// H1 image (fp16 hi only): chunk0 @0 [128][72], chunk1 @36864 [128][72], chunk2 @73728 [128][40].
// WB @98304 (73728 B region: W2 batch 47104 or W3 batch 55296).
// H2 image (fp16 hi only) @ {0, 36864}. misc @172032.
#define SSTG  41472
#define WB    98304
#define MISCO 172032
#define SMEMB (MISCO + 4096)

__global__ void __launch_bounds__(THREADS, 1) k_main(
    const float* __restrict__ b1, const float* __restrict__ b2,
    const float* __restrict__ b3, const float* __restrict__ W4,
    const float* __restrict__ b4)
{
    extern __shared__ __align__(16) unsigned char sm[];
    const int s = blockIdx.y, t = blockIdx.x, z = blockIdx.z, tid = threadIdx.x;
    const int cnt = g_count[s];
    const int ntl = (cnt + TM - 1) / TM;
    if (t >= ntl) return;
    const int nvalid = min(TM, cnt - t * TM);
    const int gt = g_tbase[s] + t;
    const int lane = tid & 31, w = tid >> 5;
    const int wm = w & 3, wn = w >> 2, g = lane >> 2, q = lane & 3;
    const int mbase = wm * 32;
    const u32 sb = s2u(sm);
    float* b1s = (float*)(sm + MISCO);
    float* b2s = b1s + 160;
    float* b3s = b2s + 128;
    float* w4s = b3s + 96;
    float* part = w4s + 96;

    const unsigned char* Ab = g_Aimg + (size_t)gt * ASE;
    float blockSum = 0.f;

    const int h1off[3] = {0, 36864, 73728};
    const int h1str[3] = {72, 72, 40};
    const int w2off[3] = {0, 18432, 36864};
    const int w2str[3] = {72, 72, 40};
    const int w2ks[3]  = {4, 4, 2};

    for (int ei = 0; ei < 2; ei++) {
        const int se = s * E_ + z * 2 + ei;
        const unsigned char* Wb = g_Wimg + (size_t)se * WSE;
        if (tid < 160) b1s[tid] = b1[se * H1_ + tid];
        if (tid < 128) b2s[tid] = b2[se * H2_ + tid];
        if (tid < 96) { b3s[tid] = b3[se * H3_ + tid]; w4s[tid] = W4[se * H3_ + tid]; }

        auto cpyW = [&](const unsigned char* src, int bytes, u32 dstoff) {
            for (int i = tid * 16; i < bytes; i += THREADS * 16) CPA16(sb + dstoff + i, src + i);
            CPCOMMIT();
        };

        // ========= Layer 1 (K=384, N=160): fp16 single-term, NT=5 per warp =========
        float acc1[2][5][4];
#pragma unroll
        for (int a = 0; a < 2; a++)
#pragma unroll
            for (int b = 0; b < 5; b++)
#pragma unroll
                for (int c = 0; c < 4; c++) acc1[a][b][c] = 0.f;

        auto cpyL1 = [&](int c, int bf) {
            u32 dst = sb + (bf ? SSTG : 0);
            const unsigned char* gA = Ab + c * ACH;            // hi half only
            for (int i = tid * 16; i < 18432; i += THREADS * 16) CPA16(dst + i, gA + i);
            const unsigned char* gW = Wb + W1OFF + c * 23040;
            for (int i = tid * 16; i < 23040; i += THREADS * 16) CPA16(dst + 18432 + i, gW + i);
            CPCOMMIT();
        };
        cpyL1(0, 0); cpyL1(1, 1);
        for (int kc = 0; kc < 6; kc++) {
            if (kc == 5) { CPWAIT(0); } else { CPWAIT(1); }
            __syncthreads();
            const unsigned char* st = sm + ((kc & 1) ? SSTG : 0);
            chunk_mma1<5>(acc1, (const u16*)st, 72,
                          (const u16*)(st + 18432), 72,
                          4, mbase, wn * 40, g, q);
            __syncthreads();
            if (kc < 4) cpyL1(kc + 2, kc & 1);
        }
        // single batch copy of ALL W2 chunks (47104 B) — overlaps with L1 epilogue
        cpyW(Wb + W2OFF, 47104, WB);

        // epilogue -> H1 (fp16 hi only)
#pragma unroll
        for (int mt = 0; mt < 2; mt++)
#pragma unroll
            for (int nt = 0; nt < 5; nt++) {
                int n0 = wn * 40 + nt * 8 + q * 2;
                int cb = n0 >> 6, off = n0 & 63;
                u16* Hh = (u16*)(sm + h1off[cb]);
                int str = h1str[cb];
                int row = mbase + mt * 16 + g;
                *(u32*)(Hh + row * str + off) =
                    packh(celu_f(acc1[mt][nt][0] + b1s[n0]),
                          celu_f(acc1[mt][nt][1] + b1s[n0 + 1]));
                *(u32*)(Hh + (row + 8) * str + off) =
                    packh(celu_f(acc1[mt][nt][2] + b1s[n0]),
                          celu_f(acc1[mt][nt][3] + b1s[n0 + 1]));
            }
        CPWAIT(0);
        __syncthreads();

        // ========= Layer 2 (K=160, N=128): fp16 single-term, NT=4 =========
        float acc2[2][4][4];
#pragma unroll
        for (int a = 0; a < 2; a++)
#pragma unroll
            for (int b = 0; b < 4; b++)
#pragma unroll
                for (int c = 0; c < 4; c++) acc2[a][b][c] = 0.f;

        for (int kc = 0; kc < 3; kc++) {
            chunk_mma1<4>(acc2,
                          (const u16*)(sm + h1off[kc]), h1str[kc],
                          (const u16*)(sm + WB + w2off[kc]), w2str[kc],
                          w2ks[kc], mbase, wn * 32, g, q);
        }
        __syncthreads();
        // single batch copy of ALL W3 chunks (55296 B) — overlaps with L2 epilogue
        cpyW(Wb + W3OFF, 55296, WB);

        // epilogue -> H2 (fp16 hi only @ {0, 36864})
#pragma unroll
        for (int mt = 0; mt < 2; mt++)
#pragma unroll
            for (int nt = 0; nt < 4; nt++) {
                int n0 = wn * 32 + nt * 8 + q * 2;
                int cb = n0 >> 6, off = n0 & 63;
                u16* Hh = (u16*)(sm + cb * 36864);
                int row = mbase + mt * 16 + g;
                *(u32*)(Hh + row * 72 + off) =
                    packh(celu_f(acc2[mt][nt][0] + b2s[n0]),
                          celu_f(acc2[mt][nt][1] + b2s[n0 + 1]));
                *(u32*)(Hh + (row + 8) * 72 + off) =
                    packh(celu_f(acc2[mt][nt][2] + b2s[n0]),
                          celu_f(acc2[mt][nt][3] + b2s[n0 + 1]));
            }
        CPWAIT(0);
        __syncthreads();

        // ========= Layer 3 (K=128, N=96): fp16 2-term-W, NT=3 =========
        float acc3[2][3][4];
#pragma unroll
        for (int a = 0; a < 2; a++)
#pragma unroll
            for (int b = 0; b < 3; b++)
#pragma unroll
                for (int c = 0; c < 4; c++) acc3[a][b][c] = 0.f;

        for (int kc = 0; kc < 2; kc++) {
            const unsigned char* wb = sm + WB + kc * 27648;
            chunk_mma_w2<3>(acc3,
                            (const u16*)(sm + kc * 36864), 72,
                            (const u16*)wb, (const u16*)wb + 6912, 72,
                            4, mbase, wn * 24, g, q);
        }
        // ========= fused L3-epilogue + Layer 4 =========
        {
            float p00 = 0.f, p01 = 0.f, p10 = 0.f, p11 = 0.f;
#pragma unroll
            for (int nt = 0; nt < 3; nt++) {
                int n0 = wn * 24 + nt * 8 + q * 2;
                float w0 = w4s[n0], w1 = w4s[n0 + 1];
                float bb0 = b3s[n0], bb1 = b3s[n0 + 1];
                p00 += celu_f(acc3[0][nt][0] + bb0) * w0 + celu_f(acc3[0][nt][1] + bb1) * w1;
                p01 += celu_f(acc3[0][nt][2] + bb0) * w0 + celu_f(acc3[0][nt][3] + bb1) * w1;
                p10 += celu_f(acc3[1][nt][0] + bb0) * w0 + celu_f(acc3[1][nt][1] + bb1) * w1;
                p11 += celu_f(acc3[1][nt][2] + bb0) * w0 + celu_f(acc3[1][nt][3] + bb1) * w1;
            }
            p00 += __shfl_xor_sync(0xffffffffu, p00, 1); p00 += __shfl_xor_sync(0xffffffffu, p00, 2);
            p01 += __shfl_xor_sync(0xffffffffu, p01, 1); p01 += __shfl_xor_sync(0xffffffffu, p01, 2);
            p10 += __shfl_xor_sync(0xffffffffu, p10, 1); p10 += __shfl_xor_sync(0xffffffffu, p10, 2);
            p11 += __shfl_xor_sync(0xffffffffu, p11, 1); p11 += __shfl_xor_sync(0xffffffffu, p11, 2);
            if (q == 0) {
                part[wn * 128 + mbase + g]          = p00;
                part[wn * 128 + mbase + g + 8]      = p01;
                part[wn * 128 + mbase + 16 + g]     = p10;
                part[wn * 128 + mbase + 16 + g + 8] = p11;
            }
        }
        __syncthreads();
        if (tid < 128) {
            float en = part[tid] + part[128 + tid] + part[256 + tid] + part[384 + tid] + b4[se];
            part[tid] = (tid < nvalid) ? en : 0.f;
        }
        __syncthreads();
        if (tid < 32) {
            float v = part[tid] + part[tid + 32] + part[tid + 64] + part[tid + 96];
            for (int o = 16; o; o >>= 1) v += __shfl_down_sync(0xffffffffu, v, o);
            if (tid == 0) blockSum += v;
        }
        __syncthreads();
    }
    if (tid == 0) g_partial[(s * NTT + t) * 4 + z] = blockSum;
}

// ---------------- final reduction ----------------
__global__ void k_reduce(float* out) {
    __shared__ double sb[256];
    int tid = threadIdx.x;
    double s = 0.0;
    for (int i = tid; i < NPART; i += 256) s += (double)g_partial[i];
    sb[tid] = s;
    __syncthreads();
    for (int st = 128; st; st >>= 1) {
        if (tid < st) sb[tid] += sb[tid + st];
        __syncthreads();
    }
    if (tid == 0) out[0] = (float)(sb[0] * (1.0 / E_));
}

// ---------------- launch ----------------
extern "C" void kernel_launch(void* const* d_in, const int* in_sizes, int n_in,
                              void* d_out, int out_size)
{
    const void*  sp  = d_in[0];
    const float* aev = (const float*)d_in[1];
    const float* W1  = (const float*)d_in[2];
    const float* b1  = (const float*)d_in[3];
    const float* W2  = (const float*)d_in[4];
    const float* b2  = (const float*)d_in[5];
    const float* W3  = (const float*)d_in[6];
    const float* b3  = (const float*)d_in[7];
    const float* W4  = (const float*)d_in[8];
    const float* b4  = (const float*)d_in[9];

    cudaFuncSetAttribute(k_main, cudaFuncAttributeMaxDynamicSharedMemorySize, SMEMB);

    k_init<<<1, 256>>>((const ull*)sp);
    k_count<<<NB, 256>>>((const int*)sp);
    k_scan<<<1, 256>>>();
    k_scatter<<<NB, 256>>>((const int*)sp);
    dim3 gw(32, 8);
    k_wprep<<<gw, 256>>>(W1, W2, W3);
    dim3 ga(NTT, S_);
    k_aprep<<<ga, 256>>>(aev);
    dim3 gm(NTT, S_, 4);
    k_main<<<gm, THREADS, SMEMB>>>(b1, b2, b3, W4, b4);
    k_reduce<<<1, 256>>>((float*)d_out);
}